// round 11
// baseline (speedup 1.0000x reference)
#include <cuda_runtime.h>
#include <cstdint>

// SpatialPool: fm [B=16, C=512, H=38, W=38] f32 (NCHW)
//   -> out [B, H*W, 9*C] f32, out[b, h*W+w, (di*3+dj)*C + c]
//      = fm[b, c, clamp(h+di-1), clamp(w+dj-1)]  (replicate pad)
//
// R11 = R7 load + R7 n-major write, double-buffered across TWO tiles
// (batches b and b+8) per CTA. cp.async for tile1 is in flight while
// tile0 is being written -> load and store DRAM traffic overlap instead
// of phase-serializing (R10 showed ordering isn't the binder; duty cycle is).

namespace {
constexpr int HH   = 38;
constexpr int C    = 512;
constexpr int CSUB = 128;        // channels per CTA
constexpr int NCG  = C / CSUB;   // 4
constexpr int NB   = 9;
constexpr int WT   = 19;         // w positions per CTA
constexpr int LW   = WT + 2;     // 21 local cols incl. halo
constexpr int NY   = 2;          // output rows per CTA
constexpr int NR   = NY + 2;     // 4 loaded rows incl. halo
constexpr int NPOS = NR * LW;    // 84 smem positions
constexpr int THREADS = 512;
constexpr int HW   = HH * HH;    // 1444
constexpr int RS4  = NB * C / 4; // 1152 float4 per (b,y,w)
constexpr int YS4  = HH * RS4;   // float4 stride for y+1
constexpr int BUF  = NPOS * CSUB;      // 10752 floats per buffer
}

__device__ __forceinline__ void cp_async4(float* smem_dst, const float* gsrc) {
    uint32_t sa = (uint32_t)__cvta_generic_to_shared(smem_dst);
    asm volatile("cp.async.ca.shared.global [%0], [%1], 4;\n"
                 :: "r"(sa), "l"(gsrc) : "memory");
}

__global__ __launch_bounds__(THREADS, 2)
void spatialpool_kernel(const float* __restrict__ fm, float* __restrict__ out) {
    // logical (pos, c) at buf[pos*128 + 4*((c>>2)^(pos&31)) + (c&3)]
    __shared__ float smP[2 * BUF];   // 86,016 B -> 2 CTAs/SM

    const int lane = threadIdx.x & 31;
    const int wid  = threadIdx.x >> 5;

    const int wh = blockIdx.x & 1;
    const int cg = blockIdx.x >> 1;        // channel group 0..3
    const int w0 = wh * WT;
    const int y0 = blockIdx.y * NY;        // first output row
    const int b0 = blockIdx.z;             // tiles: b0 and b0+8

    // ---- Precompute per-thread load pattern ONCE (shared by both tiles).
    // Thread owns p = lane + 32k (k<3), sweeps c = wid + 16m. ----
    int goff[3];   // global offset (within channel c0 plane) per k
    int swk[3];    // smem swizzle base per k
    int nk = 0;
    {
        #pragma unroll
        for (int k = 0; k < 3; ++k) {
            int p = lane + 32 * k;
            if (k == 2 && p >= NPOS) break;
            int r  = p / LW;
            int l  = p - r * LW;
            int yl = min(max(y0 - 1 + r, 0), HH - 1);
            int xg = min(max(w0 - 1 + l, 0), HH - 1);
            goff[k] = yl * HH + xg;
            swk[k]  = (p << 7) + (wid & 3);
            nk = k + 1;
        }
    }
    const int cq0 = wid >> 2;
    const size_t cgbase = (size_t)cg * CSUB * HW + (size_t)wid * HW;

    // ---- Issue loads for both tiles (one commit group each). ----
    #pragma unroll
    for (int tile = 0; tile < 2; ++tile) {
        const float* __restrict__ fc =
            fm + ((size_t)(b0 + 8 * tile) * C) * HW + cgbase;
        float* __restrict__ buf = &smP[tile * BUF];
        for (int k = 0; k < nk; ++k) {
            const float* __restrict__ g = fc + goff[k];
            #pragma unroll
            for (int m = 0; m < 8; ++m) {
                int sw = swk[k] + (((cq0 + 4 * m) ^ lane) << 2);
                cp_async4(&buf[sw], g + m * 16 * HW);
            }
        }
        asm volatile("cp.async.commit_group;\n" ::: "memory");
    }

    // ---- Write tiles; tile1's loads fly during tile0's stores. ----
    #pragma unroll
    for (int tile = 0; tile < 2; ++tile) {
        if (tile == 0) {
            asm volatile("cp.async.wait_group 1;\n" ::: "memory");
        } else {
            asm volatile("cp.async.wait_group 0;\n" ::: "memory");
        }
        __syncthreads();

        const float* __restrict__ buf = &smP[tile * BUF];
        float4* __restrict__ out4 = (float4*)out;
        const size_t rowbase =
            ((size_t)(b0 + 8 * tile) * HW + (size_t)y0 * HH + w0)
                * (size_t)RS4
            + (size_t)cg * (CSUB / 4) + lane;

        #pragma unroll
        for (int n = 0; n < NB; ++n) {
            const int di = n / 3;
            const int dj = n - di * 3;
            #pragma unroll 3
            for (int q = wid; q < NY * WT; q += THREADS / 32) {
                int o   = (q >= WT) ? 1 : 0;
                int wl  = q - WT * o;
                int pos = (o + di) * LW + wl + dj;

                const float4 v = *(const float4*)
                    &buf[(pos << 7) + ((lane ^ (pos & 31)) << 2)];
                __stcs(&out4[rowbase + (size_t)o * YS4
                             + (size_t)wl * RS4 + n * (C / 4)], v);
            }
        }
        if (tile == 0) __syncthreads();   // all warps done before reuse rules
    }
}

extern "C" void kernel_launch(void* const* d_in, const int* in_sizes, int n_in,
                              void* d_out, int out_size) {
    const float* fm = (const float*)d_in[0];
    float* out = (float*)d_out;
    (void)in_sizes; (void)n_in; (void)out_size;

    dim3 grid(2 * NCG, HH / NY, 8);   // (8, 19, 8) = 1216 CTAs x 2 tiles
    spatialpool_kernel<<<grid, THREADS>>>(fm, out);
}